// round 11
// baseline (speedup 1.0000x reference)
#include <cuda_runtime.h>
#include <cuda_fp16.h>
#include <cstdint>
#include <math.h>

// Problem dims
#define BDIM 1024
#define UDIM 2048
#define KDIM 4096   // 2*U
#define NDIM 8192   // 4*U

// GEMM tiling: CTA 128x128 (M x [4 gates x 32 u]), 8 warps of 64x32, BK=64
#define MT 128
#define NT 128
#define BK 64
#define PA 72                     // smem pitch in halves (144B rows, ldsm conflict-free)
#define A_HALVES (MT * PA)
#define B_HALVES (NT * PA)
#define STAGE_HALVES (A_HALVES + B_HALVES)
#define NSTG 3
#define SMEM_BYTES (NSTG * STAGE_HALVES * 2) // 110592 B -> 2 CTAs/SM
#define NCHUNK (KDIM / BK)        // 64
#define NTHREADS 256

// Static device scratch (fp16 operands)
__device__ __half g_a[(size_t)BDIM * KDIM];                // 8 MB  [m][k]
__device__ __half g_wT[(size_t)NDIM * KDIM];               // 64 MB [n][k]

// f16-accumulator MMA (tests the half-rate-f32acc hypothesis)
__device__ __forceinline__ void mma_f16acc(uint32_t d[2], const uint32_t a[4],
                                           const uint32_t b0, const uint32_t b1,
                                           const uint32_t c0, const uint32_t c1) {
    asm volatile(
        "mma.sync.aligned.m16n8k16.row.col.f16.f16.f16.f16 "
        "{%0,%1}, {%2,%3,%4,%5}, {%6,%7}, {%8,%9};"
        : "=r"(d[0]), "=r"(d[1])
        : "r"(a[0]), "r"(a[1]), "r"(a[2]), "r"(a[3]),
          "r"(b0), "r"(b1), "r"(c0), "r"(c1));
}
__device__ __forceinline__ void ldsm_x4(uint32_t r[4], uint32_t addr) {
    asm volatile("ldmatrix.sync.aligned.m8n8.x4.shared.b16 {%0,%1,%2,%3}, [%4];"
        : "=r"(r[0]), "=r"(r[1]), "=r"(r[2]), "=r"(r[3]) : "r"(addr));
}
__device__ __forceinline__ void cp16(uint32_t saddr, const void* gaddr) {
    asm volatile("cp.async.cg.shared.global [%0], [%1], 16;" :: "r"(saddr), "l"(gaddr));
}
#define CP_COMMIT() asm volatile("cp.async.commit_group;" ::: "memory")
#define CP_WAIT(N)  asm volatile("cp.async.wait_group %0;" :: "n"(N) : "memory")

// ---------------- Convert kernels ----------------
__global__ __launch_bounds__(256)
void convert_a_kernel(const float* __restrict__ x, const float* __restrict__ h) {
    const int idx = blockIdx.x * blockDim.x + threadIdx.x;
    const int m = idx >> 9;
    const int col = (idx & 511) * 8;
    const float* src = (col < UDIM) ? (x + (size_t)m * UDIM + col)
                                    : (h + (size_t)m * UDIM + col - UDIM);
    float4 v0 = *(const float4*)src;
    float4 v1 = *(const float4*)(src + 4);
    __half2 o0 = __floats2half2_rn(v0.x, v0.y);
    __half2 o1 = __floats2half2_rn(v0.z, v0.w);
    __half2 o2 = __floats2half2_rn(v1.x, v1.y);
    __half2 o3 = __floats2half2_rn(v1.z, v1.w);
    uint4 pk = make_uint4(*(uint32_t*)&o0, *(uint32_t*)&o1, *(uint32_t*)&o2, *(uint32_t*)&o3);
    *(uint4*)&g_a[(size_t)m * KDIM + col] = pk;
}

__global__ __launch_bounds__(256)
void convert_wT_kernel(const float* __restrict__ w) {
    __shared__ float tile[32][33];
    const int tx = threadIdx.x & 31;
    const int ty = threadIdx.x >> 5;
    const int kt = blockIdx.x * 32;
    const int nt = blockIdx.y * 32;
    #pragma unroll
    for (int j = 0; j < 4; j++) {
        const int k = kt + ty + j * 8;
        tile[ty + j * 8][tx] = w[(size_t)k * NDIM + nt + tx];
    }
    __syncthreads();
    #pragma unroll
    for (int j = 0; j < 4; j++) {
        const int n = nt + ty + j * 8;
        g_wT[(size_t)n * KDIM + kt + tx] = __float2half_rn(tile[tx][ty + j * 8]);
    }
}

// ---------------- Fused GEMM + LSTM gating ----------------
__device__ __forceinline__ float sigf(float v) { return 1.0f / (1.0f + expf(-v)); }

__global__ __launch_bounds__(NTHREADS, 2)
void lstm_gemm_fused(const float* __restrict__ c_in, float* __restrict__ out) {
    extern __shared__ __half smem[];
    const uint32_t sbase = (uint32_t)__cvta_generic_to_shared(smem);

    const int tid = threadIdx.x;
    const int wid = tid >> 5;
    const int lane = tid & 31;
    const int warp_m = wid & 1;       // 0..1 -> 64 rows
    const int warp_n = wid >> 1;      // 0..3 -> u-strip of 8 (x 4 gates)

    const int m0 = blockIdx.x * MT;   // M fastest
    const int u0 = blockIdx.y * 32;   // u strip (2048/32 = 64)

    // ldmatrix lane offsets (verified in R8)
    const int a_lane = (lane & 15) * PA + ((lane & 16) >> 1);
    const int b_lane = ((lane & 7) + ((lane & 16) >> 1)) * PA + (lane & 8);
    const uint32_t a_warp = (uint32_t)(warp_m * 64) * PA;
    const uint32_t b_warp = (uint32_t)(warp_n * 32) * PA;

    // f32 master accumulators: [mt][gate][4]
    float facc[4][4][4];
    #pragma unroll
    for (int mt = 0; mt < 4; mt++)
        #pragma unroll
        for (int g = 0; g < 4; g++)
            #pragma unroll
            for (int r = 0; r < 4; r++) facc[mt][g][r] = 0.f;

    // cp.async mapping: 2 threads per 128B row
    const int cprow = tid >> 1;              // 0..127
    const int cpseg = (tid & 1) * 4;         // 0 or 4
    // B gather: smem row (wn*32 + gate*8 + uoff) <- g_wT row gate*2048 + u0 + wn*8 + uoff
    const int b_wn   = cprow >> 5;
    const int b_j    = cprow & 31;
    const int b_gate = b_j >> 3;
    const size_t b_nglob = (size_t)b_gate * UDIM + u0 + b_wn * 8 + (b_j & 7);

    auto issue_chunk = [&](int c) {
        const int k0 = c * BK;
        const uint32_t st = sbase + (uint32_t)(c % NSTG) * (STAGE_HALVES * 2);
        const __half* ga = g_a + (size_t)(m0 + cprow) * KDIM + k0 + cpseg * 8;
        const __half* gb = g_wT + b_nglob * KDIM + k0 + cpseg * 8;
        const uint32_t sa = st + (uint32_t)cprow * (PA * 2) + cpseg * 16;
        const uint32_t sb = st + A_HALVES * 2 + (uint32_t)cprow * (PA * 2) + cpseg * 16;
        #pragma unroll
        for (int s = 0; s < 4; s++) cp16(sa + s * 16, ga + s * 8);
        #pragma unroll
        for (int s = 0; s < 4; s++) cp16(sb + s * 16, gb + s * 8);
        CP_COMMIT();
    };

    auto compute_chunk = [&](int c) {
        const uint32_t st = sbase + (uint32_t)(c % NSTG) * (STAGE_HALVES * 2);
        const uint32_t abase = st + 2 * (a_warp + a_lane);
        const uint32_t bbase = st + A_HALVES * 2 + 2 * (b_warp + b_lane);
        uint32_t cacc[4][4][2];   // f16 chunk accumulators
        #pragma unroll
        for (int ks = 0; ks < 4; ks++) {
            const uint32_t kb = ks * 32;   // bytes
            uint32_t af[4][4], bq[2][4];
            #pragma unroll
            for (int mt = 0; mt < 4; mt++)
                ldsm_x4(af[mt], abase + (uint32_t)mt * (16 * PA * 2) + kb);
            #pragma unroll
            for (int np = 0; np < 2; np++)
                ldsm_x4(bq[np], bbase + (uint32_t)np * (16 * PA * 2) + kb);
            #pragma unroll
            for (int mt = 0; mt < 4; mt++)
                #pragma unroll
                for (int np = 0; np < 2; np++) {
                    if (ks == 0) {
                        mma_f16acc(cacc[mt][2*np],   af[mt], bq[np][0], bq[np][1], 0u, 0u);
                        mma_f16acc(cacc[mt][2*np+1], af[mt], bq[np][2], bq[np][3], 0u, 0u);
                    } else {
                        mma_f16acc(cacc[mt][2*np],   af[mt], bq[np][0], bq[np][1],
                                   cacc[mt][2*np][0], cacc[mt][2*np][1]);
                        mma_f16acc(cacc[mt][2*np+1], af[mt], bq[np][2], bq[np][3],
                                   cacc[mt][2*np+1][0], cacc[mt][2*np+1][1]);
                    }
                }
        }
        // promote chunk result to f32
        #pragma unroll
        for (int mt = 0; mt < 4; mt++)
            #pragma unroll
            for (int g = 0; g < 4; g++) {
                float2 f0 = __half22float2(*(const half2*)&cacc[mt][g][0]);
                float2 f1 = __half22float2(*(const half2*)&cacc[mt][g][1]);
                facc[mt][g][0] += f0.x;
                facc[mt][g][1] += f0.y;
                facc[mt][g][2] += f1.x;
                facc[mt][g][3] += f1.y;
            }
    };

    issue_chunk(0);
    issue_chunk(1);

    #pragma unroll 1
    for (int c = 0; c < NCHUNK; c++) {
        if (c + 2 < NCHUNK) { CP_WAIT(1); }
        else                { CP_WAIT(0); }
        __syncthreads();
        if (c + 2 < NCHUNK) issue_chunk(c + 2);
        compute_chunk(c);
    }

    // ---- fused LSTM gating epilogue (i,f,g,o live in registers) ----
    const size_t BU = (size_t)BDIM * UDIM;
    const int u_t = u0 + warp_n * 8 + 2 * (lane & 3);
    #pragma unroll
    for (int mt = 0; mt < 4; mt++) {
        const int row = m0 + warp_m * 64 + mt * 16 + (lane >> 2);
        #pragma unroll
        for (int half_idx = 0; half_idx < 2; half_idx++) {   // row, row+8
            const int r = row + half_idx * 8;
            const int e0 = half_idx * 2;
            const float2 cv = *(const float2*)&c_in[(size_t)r * UDIM + u_t];
            float hn[2], cn[2];
            #pragma unroll
            for (int e = 0; e < 2; e++) {
                const float ig = sigf(facc[mt][0][e0 + e]);
                const float fg = sigf(facc[mt][1][e0 + e]);
                const float gg = tanhf(facc[mt][2][e0 + e]);
                const float og = sigf(facc[mt][3][e0 + e]);
                const float cc = (e == 0) ? cv.x : cv.y;
                cn[e] = fg * cc + ig * gg;
                hn[e] = og * tanhf(cn[e]);
            }
            const size_t o = (size_t)r * UDIM + u_t;
            float2 hv = make_float2(hn[0], hn[1]);
            float2 cnv = make_float2(cn[0], cn[1]);
            *(float2*)&out[o] = hv;
            *(float2*)&out[BU + o] = hv;
            *(float2*)&out[2 * BU + o] = cnv;
        }
    }
}

// ---------------- Launch ----------------
extern "C" void kernel_launch(void* const* d_in, const int* in_sizes, int n_in,
                              void* d_out, int out_size) {
    const float* x = (const float*)d_in[0];
    const float* h = (const float*)d_in[1];
    const float* c = (const float*)d_in[2];
    const float* w = (const float*)d_in[3];
    float* out = (float*)d_out;

    cudaFuncSetAttribute(lstm_gemm_fused, cudaFuncAttributeMaxDynamicSharedMemorySize, SMEM_BYTES);

    convert_a_kernel<<<(BDIM * KDIM / 8) / 256, 256>>>(x, h);

    dim3 tgrid(KDIM / 32, NDIM / 32);   // (128, 256)
    convert_wT_kernel<<<tgrid, 256>>>(w);

    dim3 grid(BDIM / MT, UDIM / 32);    // (8, 64), M fastest
    lstm_gemm_fused<<<grid, NTHREADS, SMEM_BYTES>>>(c, out);
}

// round 12
// speedup vs baseline: 1.2425x; 1.2425x over previous
#include <cuda_runtime.h>
#include <cuda_fp16.h>
#include <cstdint>
#include <math.h>

// Problem dims
#define BDIM 1024
#define UDIM 2048
#define KDIM 4096   // 2*U
#define NDIM 8192   // 4*U

// GEMM tiling (R7-proven): CTA 128x128, 8 warps of 64x32, BK=32, NSTG=5
#define MT 128
#define NT 128
#define BK 32
#define PA 40                     // smem pitch in halves
#define A_HALVES (MT * PA)        // 5120
#define B_HALVES (NT * PA)        // 5120
#define STAGE_HALVES (A_HALVES + B_HALVES)   // 10240 (20480 B)
#define NSTG 5
#define SMEM_BYTES (NSTG * STAGE_HALVES * 2) // 102400 B
#define NCHUNK (KDIM / BK)        // 128
#define NTHREADS 256

// Static device scratch (fp16 operands)
__device__ __half g_a[(size_t)BDIM * KDIM];                // 8 MB  [m][k]
__device__ __half g_wT[(size_t)NDIM * KDIM];               // 64 MB [n][k]

__device__ __forceinline__ void mma_f16(float d[4], const uint32_t a[4],
                                        const uint32_t b0, const uint32_t b1) {
    asm volatile(
        "mma.sync.aligned.m16n8k16.row.col.f32.f16.f16.f32 "
        "{%0,%1,%2,%3}, {%4,%5,%6,%7}, {%8,%9}, {%0,%1,%2,%3};"
        : "+f"(d[0]), "+f"(d[1]), "+f"(d[2]), "+f"(d[3])
        : "r"(a[0]), "r"(a[1]), "r"(a[2]), "r"(a[3]), "r"(b0), "r"(b1));
}
__device__ __forceinline__ void cp16(uint32_t saddr, const void* gaddr) {
    asm volatile("cp.async.cg.shared.global [%0], [%1], 16;" :: "r"(saddr), "l"(gaddr));
}
#define CP_COMMIT() asm volatile("cp.async.commit_group;" ::: "memory")
#define CP_WAIT(N)  asm volatile("cp.async.wait_group %0;" :: "n"(N) : "memory")

// ---------------- Convert kernels ----------------
// A: concat(x,h) -> fp16, 16 elems/thread (MLP 4)
__global__ __launch_bounds__(256)
void convert_a_kernel(const float* __restrict__ x, const float* __restrict__ h) {
    const int idx = blockIdx.x * blockDim.x + threadIdx.x;   // over B*K/16
    const int m = idx >> 8;                                  // 4096/16 = 256 groups/row
    const int col = (idx & 255) * 16;
    const float* src = (col < UDIM) ? (x + (size_t)m * UDIM + col)
                                    : (h + (size_t)m * UDIM + col - UDIM);
    float4 v0 = *(const float4*)(src + 0);
    float4 v1 = *(const float4*)(src + 4);
    float4 v2 = *(const float4*)(src + 8);
    float4 v3 = *(const float4*)(src + 12);
    __half2 a0 = __floats2half2_rn(v0.x, v0.y), a1 = __floats2half2_rn(v0.z, v0.w);
    __half2 a2 = __floats2half2_rn(v1.x, v1.y), a3 = __floats2half2_rn(v1.z, v1.w);
    __half2 a4 = __floats2half2_rn(v2.x, v2.y), a5 = __floats2half2_rn(v2.z, v2.w);
    __half2 a6 = __floats2half2_rn(v3.x, v3.y), a7 = __floats2half2_rn(v3.z, v3.w);
    uint4 p0 = make_uint4(*(uint32_t*)&a0, *(uint32_t*)&a1, *(uint32_t*)&a2, *(uint32_t*)&a3);
    uint4 p1 = make_uint4(*(uint32_t*)&a4, *(uint32_t*)&a5, *(uint32_t*)&a6, *(uint32_t*)&a7);
    *(uint4*)&g_a[(size_t)m * KDIM + col] = p0;
    *(uint4*)&g_a[(size_t)m * KDIM + col + 8] = p1;
}

// w[k][n] fp32 -> g_wT[n][k] fp16; tile 64k x 32n; coalesced both sides
__global__ __launch_bounds__(256)
void convert_wT_kernel(const float* __restrict__ w) {
    __shared__ float tile[64][33];
    const int kt = blockIdx.x * 64;
    const int nt = blockIdx.y * 32;
    const int r = threadIdx.x >> 5;     // 0..7
    const int cidx = threadIdx.x & 31;
    #pragma unroll
    for (int j = 0; j < 8; j++)
        tile[r + j * 8][cidx] = w[(size_t)(kt + r + j * 8) * NDIM + nt + cidx];
    __syncthreads();
    const int n = threadIdx.x >> 3;     // 0..31
    const int gseg = threadIdx.x & 7;   // 0..7 (k-groups of 8)
    __half2 hp[4];
    #pragma unroll
    for (int i = 0; i < 4; i++)
        hp[i] = __floats2half2_rn(tile[gseg * 8 + 2 * i][n], tile[gseg * 8 + 2 * i + 1][n]);
    uint4 pk = make_uint4(*(uint32_t*)&hp[0], *(uint32_t*)&hp[1],
                          *(uint32_t*)&hp[2], *(uint32_t*)&hp[3]);
    *(uint4*)&g_wT[(size_t)(nt + n) * KDIM + kt + gseg * 8] = pk;
}

// ---------------- Fused GEMM + LSTM gating ----------------
__device__ __forceinline__ float sigf(float v) { return 1.0f / (1.0f + expf(-v)); }

__global__ __launch_bounds__(NTHREADS, 2)
void lstm_gemm_fused(const float* __restrict__ c_in, float* __restrict__ out) {
    extern __shared__ __half smem[];
    const uint32_t sbase = (uint32_t)__cvta_generic_to_shared(smem);

    const int tid = threadIdx.x;
    const int wid = tid >> 5;
    const int lane = tid & 31;
    const int warp_m = wid >> 2;      // 0..1 -> 64 rows
    const int warp_n = wid & 3;       // 0..3 -> u-strip of 8 (x 4 gates)

    const int m0 = blockIdx.x * MT;   // M fastest
    const int u0 = blockIdx.y * 32;   // u strip

    float acc[4][4][4];               // [mt][gate][reg]
    #pragma unroll
    for (int mt = 0; mt < 4; mt++)
        #pragma unroll
        for (int g = 0; g < 4; g++)
            #pragma unroll
            for (int r = 0; r < 4; r++) acc[mt][g][r] = 0.f;

    // cp.async: 2 threads per 64B row (BK=32 halves); each thread 2x16B
    const int cprow = tid >> 1;              // 0..127
    const int cpseg = (tid & 1) * 2;         // 0 or 2
    // gate-interleaved B gather: smem row r -> g_wT row gate*U + u0 + wn*8 + uoff
    const int b_wn   = cprow >> 5;
    const int b_j    = cprow & 31;
    const int b_gate = b_j >> 3;
    const size_t b_nglob = (size_t)b_gate * UDIM + u0 + b_wn * 8 + (b_j & 7);

    auto issue_chunk = [&](int c) {
        const int k0 = c * BK;
        const uint32_t st = sbase + (uint32_t)(c % NSTG) * (STAGE_HALVES * 2);
        const __half* ga = g_a + (size_t)(m0 + cprow) * KDIM + k0 + cpseg * 8;
        const __half* gb = g_wT + b_nglob * KDIM + k0 + cpseg * 8;
        const uint32_t sa = st + (uint32_t)cprow * (PA * 2) + cpseg * 16;
        const uint32_t sb = st + A_HALVES * 2 + (uint32_t)cprow * (PA * 2) + cpseg * 16;
        cp16(sa, ga);
        cp16(sa + 16, ga + 8);
        cp16(sb, gb);
        cp16(sb + 16, gb + 8);
        CP_COMMIT();
    };

    auto compute_ks = [&](int c, int ks) {
        const __half* As = smem + (size_t)(c % NSTG) * STAGE_HALVES;
        const __half* Bs = As + A_HALVES;
        const int kb = ks * 16 + 2 * (lane & 3);
        uint32_t af[4][4], bf[4][2];
        #pragma unroll
        for (int mt = 0; mt < 4; mt++) {
            const int r0 = warp_m * 64 + mt * 16 + (lane >> 2);
            const __half* ap = As + r0 * PA + kb;
            af[mt][0] = *(const uint32_t*)ap;
            af[mt][1] = *(const uint32_t*)(ap + 8 * PA);
            af[mt][2] = *(const uint32_t*)(ap + 8);
            af[mt][3] = *(const uint32_t*)(ap + 8 * PA + 8);
        }
        #pragma unroll
        for (int g = 0; g < 4; g++) {
            const int nn = warp_n * 32 + g * 8 + (lane >> 2);
            const __half* bp = Bs + nn * PA + kb;
            bf[g][0] = *(const uint32_t*)bp;
            bf[g][1] = *(const uint32_t*)(bp + 8);
        }
        #pragma unroll
        for (int mt = 0; mt < 4; mt++)
            #pragma unroll
            for (int g = 0; g < 4; g++)
                mma_f16(acc[mt][g], af[mt], bf[g][0], bf[g][1]);
    };

    // prologue: fill NSTG-1 stages
    #pragma unroll
    for (int c = 0; c < NSTG - 1; c++) issue_chunk(c);

    #pragma unroll 1
    for (int c = 0; c < NCHUNK; c++) {
        if (c + NSTG - 1 < NCHUNK) { CP_WAIT(3); }
        else                       { CP_WAIT(0); }   // drain fully at tail (race fix)
        __syncthreads();
        compute_ks(c, 0);
        if (c + NSTG - 1 < NCHUNK) issue_chunk(c + NSTG - 1);
        compute_ks(c, 1);
    }

    // ---- fused LSTM gating epilogue ----
    const size_t BU = (size_t)BDIM * UDIM;
    const int u_t = u0 + warp_n * 8 + 2 * (lane & 3);
    #pragma unroll
    for (int mt = 0; mt < 4; mt++) {
        const int row = m0 + warp_m * 64 + mt * 16 + (lane >> 2);
        #pragma unroll
        for (int half_idx = 0; half_idx < 2; half_idx++) {
            const int r = row + half_idx * 8;
            const int e0 = half_idx * 2;
            const float2 cv = *(const float2*)&c_in[(size_t)r * UDIM + u_t];
            float hn[2], cn[2];
            #pragma unroll
            for (int e = 0; e < 2; e++) {
                const float ig = sigf(acc[mt][0][e0 + e]);
                const float fg = sigf(acc[mt][1][e0 + e]);
                const float gg = tanhf(acc[mt][2][e0 + e]);
                const float og = sigf(acc[mt][3][e0 + e]);
                const float cc = (e == 0) ? cv.x : cv.y;
                cn[e] = fg * cc + ig * gg;
                hn[e] = og * tanhf(cn[e]);
            }
            const size_t o = (size_t)r * UDIM + u_t;
            float2 hv = make_float2(hn[0], hn[1]);
            float2 cnv = make_float2(cn[0], cn[1]);
            *(float2*)&out[o] = hv;
            *(float2*)&out[BU + o] = hv;
            *(float2*)&out[2 * BU + o] = cnv;
        }
    }
}

// ---------------- Launch ----------------
extern "C" void kernel_launch(void* const* d_in, const int* in_sizes, int n_in,
                              void* d_out, int out_size) {
    const float* x = (const float*)d_in[0];
    const float* h = (const float*)d_in[1];
    const float* c = (const float*)d_in[2];
    const float* w = (const float*)d_in[3];
    float* out = (float*)d_out;

    cudaFuncSetAttribute(lstm_gemm_fused, cudaFuncAttributeMaxDynamicSharedMemorySize, SMEM_BYTES);

    convert_a_kernel<<<(BDIM * KDIM / 16) / 256, 256>>>(x, h);

    dim3 tgrid(KDIM / 64, NDIM / 32);   // (64, 256)
    convert_wT_kernel<<<tgrid, 256>>>(w);

    dim3 grid(BDIM / MT, UDIM / 32);    // (8, 64), M fastest
    lstm_gemm_fused<<<grid, NTHREADS, SMEM_BYTES>>>(c, out);
}

// round 13
// speedup vs baseline: 1.2670x; 1.0197x over previous
#include <cuda_runtime.h>
#include <cuda_fp16.h>
#include <cstdint>
#include <math.h>

// Problem dims
#define BDIM 1024
#define UDIM 2048
#define KDIM 4096   // 2*U
#define NDIM 8192   // 4*U

// GEMM tiling: CTA 128x128, 16 warps of 32x32, BK=32, NSTG=5
#define MT 128
#define NT 128
#define BK 32
#define PA 40                     // smem pitch in halves
#define A_HALVES (MT * PA)        // 5120
#define B_HALVES (NT * PA)        // 5120
#define STAGE_HALVES (A_HALVES + B_HALVES)   // 10240 (20480 B)
#define NSTG 5
#define SMEM_BYTES (NSTG * STAGE_HALVES * 2) // 102400 B
#define NCHUNK (KDIM / BK)        // 128
#define NTHREADS 512

// Static device scratch (fp16 operands)
__device__ __half g_a[(size_t)BDIM * KDIM];                // 8 MB  [m][k]
__device__ __half g_wT[(size_t)NDIM * KDIM];               // 64 MB [n][k]

__device__ __forceinline__ void mma_f16(float d[4], const uint32_t a[4],
                                        const uint32_t b0, const uint32_t b1) {
    asm volatile(
        "mma.sync.aligned.m16n8k16.row.col.f32.f16.f16.f32 "
        "{%0,%1,%2,%3}, {%4,%5,%6,%7}, {%8,%9}, {%0,%1,%2,%3};"
        : "+f"(d[0]), "+f"(d[1]), "+f"(d[2]), "+f"(d[3])
        : "r"(a[0]), "r"(a[1]), "r"(a[2]), "r"(a[3]), "r"(b0), "r"(b1));
}
__device__ __forceinline__ void cp16(uint32_t saddr, const void* gaddr) {
    asm volatile("cp.async.cg.shared.global [%0], [%1], 16;" :: "r"(saddr), "l"(gaddr));
}
#define CP_COMMIT() asm volatile("cp.async.commit_group;" ::: "memory")
#define CP_WAIT(N)  asm volatile("cp.async.wait_group %0;" :: "n"(N) : "memory")

// ---------------- Convert kernels ----------------
__global__ __launch_bounds__(256)
void convert_a_kernel(const float* __restrict__ x, const float* __restrict__ h) {
    const int idx = blockIdx.x * blockDim.x + threadIdx.x;   // over B*K/16
    const int m = idx >> 8;
    const int col = (idx & 255) * 16;
    const float* src = (col < UDIM) ? (x + (size_t)m * UDIM + col)
                                    : (h + (size_t)m * UDIM + col - UDIM);
    float4 v0 = *(const float4*)(src + 0);
    float4 v1 = *(const float4*)(src + 4);
    float4 v2 = *(const float4*)(src + 8);
    float4 v3 = *(const float4*)(src + 12);
    __half2 a0 = __floats2half2_rn(v0.x, v0.y), a1 = __floats2half2_rn(v0.z, v0.w);
    __half2 a2 = __floats2half2_rn(v1.x, v1.y), a3 = __floats2half2_rn(v1.z, v1.w);
    __half2 a4 = __floats2half2_rn(v2.x, v2.y), a5 = __floats2half2_rn(v2.z, v2.w);
    __half2 a6 = __floats2half2_rn(v3.x, v3.y), a7 = __floats2half2_rn(v3.z, v3.w);
    uint4 p0 = make_uint4(*(uint32_t*)&a0, *(uint32_t*)&a1, *(uint32_t*)&a2, *(uint32_t*)&a3);
    uint4 p1 = make_uint4(*(uint32_t*)&a4, *(uint32_t*)&a5, *(uint32_t*)&a6, *(uint32_t*)&a7);
    *(uint4*)&g_a[(size_t)m * KDIM + col] = p0;
    *(uint4*)&g_a[(size_t)m * KDIM + col + 8] = p1;
}

__global__ __launch_bounds__(256)
void convert_wT_kernel(const float* __restrict__ w) {
    __shared__ float tile[64][33];
    const int kt = blockIdx.x * 64;
    const int nt = blockIdx.y * 32;
    const int r = threadIdx.x >> 5;
    const int cidx = threadIdx.x & 31;
    #pragma unroll
    for (int j = 0; j < 8; j++)
        tile[r + j * 8][cidx] = w[(size_t)(kt + r + j * 8) * NDIM + nt + cidx];
    __syncthreads();
    const int n = threadIdx.x >> 3;
    const int gseg = threadIdx.x & 7;
    __half2 hp[4];
    #pragma unroll
    for (int i = 0; i < 4; i++)
        hp[i] = __floats2half2_rn(tile[gseg * 8 + 2 * i][n], tile[gseg * 8 + 2 * i + 1][n]);
    uint4 pk = make_uint4(*(uint32_t*)&hp[0], *(uint32_t*)&hp[1],
                          *(uint32_t*)&hp[2], *(uint32_t*)&hp[3]);
    *(uint4*)&g_wT[(size_t)(nt + n) * KDIM + kt + gseg * 8] = pk;
}

// ---------------- Fused GEMM + LSTM gating ----------------
__device__ __forceinline__ float sigf(float v) { return 1.0f / (1.0f + expf(-v)); }

__global__ __launch_bounds__(NTHREADS, 2)
void lstm_gemm_fused(const float* __restrict__ c_in, float* __restrict__ out) {
    extern __shared__ __half smem[];
    const uint32_t sbase = (uint32_t)__cvta_generic_to_shared(smem);

    const int tid = threadIdx.x;
    const int wid = tid >> 5;
    const int lane = tid & 31;
    const int warp_m = wid >> 2;      // 0..3 -> 32-row strip
    const int warp_n = wid & 3;       // 0..3 -> u-strip of 8 (x 4 gates)

    const int m0 = blockIdx.x * MT;   // M fastest
    const int u0 = blockIdx.y * 32;   // u strip

    float acc[2][4][4];               // [mt][gate][reg] -> 32 regs
    #pragma unroll
    for (int mt = 0; mt < 2; mt++)
        #pragma unroll
        for (int g = 0; g < 4; g++)
            #pragma unroll
            for (int r = 0; r < 4; r++) acc[mt][g][r] = 0.f;

    // cp.async: 4 threads per 64B row; each thread 1x16B for A and 1x16B for B
    const int cprow = tid >> 2;              // 0..127
    const int cpseg = tid & 3;               // 16B seg
    // gate-interleaved B gather: smem row r -> g_wT row gate*U + u0 + wn*8 + uoff
    const int b_wn   = cprow >> 5;
    const int b_j    = cprow & 31;
    const int b_gate = b_j >> 3;
    const size_t b_nglob = (size_t)b_gate * UDIM + u0 + b_wn * 8 + (b_j & 7);

    auto issue_chunk = [&](int c) {
        const int k0 = c * BK;
        const uint32_t st = sbase + (uint32_t)(c % NSTG) * (STAGE_HALVES * 2);
        const __half* ga = g_a + (size_t)(m0 + cprow) * KDIM + k0 + cpseg * 8;
        const __half* gb = g_wT + b_nglob * KDIM + k0 + cpseg * 8;
        const uint32_t sa = st + (uint32_t)cprow * (PA * 2) + cpseg * 16;
        const uint32_t sb = st + A_HALVES * 2 + (uint32_t)cprow * (PA * 2) + cpseg * 16;
        cp16(sa, ga);
        cp16(sb, gb);
        CP_COMMIT();
    };

    auto compute_ks = [&](int c, int ks) {
        const __half* As = smem + (size_t)(c % NSTG) * STAGE_HALVES;
        const __half* Bs = As + A_HALVES;
        const int kb = ks * 16 + 2 * (lane & 3);
        uint32_t af[2][4];
        #pragma unroll
        for (int mt = 0; mt < 2; mt++) {
            const int r0 = warp_m * 32 + mt * 16 + (lane >> 2);
            const __half* ap = As + r0 * PA + kb;
            af[mt][0] = *(const uint32_t*)ap;
            af[mt][1] = *(const uint32_t*)(ap + 8 * PA);
            af[mt][2] = *(const uint32_t*)(ap + 8);
            af[mt][3] = *(const uint32_t*)(ap + 8 * PA + 8);
        }
        #pragma unroll
        for (int g = 0; g < 4; g++) {
            const int nn = warp_n * 32 + g * 8 + (lane >> 2);
            const __half* bp = Bs + nn * PA + kb;
            const uint32_t b0 = *(const uint32_t*)bp;
            const uint32_t b1 = *(const uint32_t*)(bp + 8);
            mma_f16(acc[0][g], af[0], b0, b1);
            mma_f16(acc[1][g], af[1], b0, b1);
        }
    };

    // prologue: fill NSTG-1 stages
    #pragma unroll
    for (int c = 0; c < NSTG - 1; c++) issue_chunk(c);

    #pragma unroll 1
    for (int c = 0; c < NCHUNK; c++) {
        if (c + NSTG - 1 < NCHUNK) { CP_WAIT(3); }
        else                       { CP_WAIT(0); }   // drain fully at tail
        __syncthreads();
        compute_ks(c, 0);
        if (c + NSTG - 1 < NCHUNK) issue_chunk(c + NSTG - 1);
        compute_ks(c, 1);
    }

    // ---- fused LSTM gating epilogue ----
    const size_t BU = (size_t)BDIM * UDIM;
    const int u_t = u0 + warp_n * 8 + 2 * (lane & 3);
    #pragma unroll
    for (int mt = 0; mt < 2; mt++) {
        const int row = m0 + warp_m * 32 + mt * 16 + (lane >> 2);
        #pragma unroll
        for (int half_idx = 0; half_idx < 2; half_idx++) {
            const int r = row + half_idx * 8;
            const int e0 = half_idx * 2;
            const float2 cv = *(const float2*)&c_in[(size_t)r * UDIM + u_t];
            float hn[2], cn[2];
            #pragma unroll
            for (int e = 0; e < 2; e++) {
                const float ig = sigf(acc[mt][0][e0 + e]);
                const float fg = sigf(acc[mt][1][e0 + e]);
                const float gg = tanhf(acc[mt][2][e0 + e]);
                const float og = sigf(acc[mt][3][e0 + e]);
                const float cc = (e == 0) ? cv.x : cv.y;
                cn[e] = fg * cc + ig * gg;
                hn[e] = og * tanhf(cn[e]);
            }
            const size_t o = (size_t)r * UDIM + u_t;
            float2 hv = make_float2(hn[0], hn[1]);
            float2 cnv = make_float2(cn[0], cn[1]);
            *(float2*)&out[o] = hv;
            *(float2*)&out[BU + o] = hv;
            *(float2*)&out[2 * BU + o] = cnv;
        }
    }
}

// ---------------- Launch ----------------
extern "C" void kernel_launch(void* const* d_in, const int* in_sizes, int n_in,
                              void* d_out, int out_size) {
    const float* x = (const float*)d_in[0];
    const float* h = (const float*)d_in[1];
    const float* c = (const float*)d_in[2];
    const float* w = (const float*)d_in[3];
    float* out = (float*)d_out;

    cudaFuncSetAttribute(lstm_gemm_fused, cudaFuncAttributeMaxDynamicSharedMemorySize, SMEM_BYTES);

    convert_a_kernel<<<(BDIM * KDIM / 16) / 256, 256>>>(x, h);

    dim3 tgrid(KDIM / 64, NDIM / 32);   // (64, 256)
    convert_wT_kernel<<<tgrid, 256>>>(w);

    dim3 grid(BDIM / MT, UDIM / 32);    // (8, 64), M fastest
    lstm_gemm_fused<<<grid, NTHREADS, SMEM_BYTES>>>(c, out);
}